// round 4
// baseline (speedup 1.0000x reference)
#include <cuda_runtime.h>

#define MAXROWS 32768
#define MAXPART 8192
#define BLK 256

__device__ float g_mask[MAXROWS];   // 1.0 if row valid else 0.0
__device__ float g_corr[MAXROWS];   // masked ((l1p_t - lp_t)/W + (l1p_t - lp_t)/H)
__device__ float g_part[MAXPART];   // per-block partials of -invL * sum(mask * l1p)

__device__ __forceinline__ float clog1m(float p) {
    // clamp(log(1-p), -100)  (torch BCELoss style clamp)
    return fmaxf(__logf(1.0f - p), -100.0f);
}

__device__ __forceinline__ float mask_of(longlong2 t) {
    // After clamping to [0, L-1], tx==0 iff t.x<=0 (same for y).
    // valid = !(tx==0 && ty==0)  =>  (t.x > 0) || (t.y > 0)
    return (t.x > 0 || t.y > 0) ? 1.0f : 0.0f;
}

// ---------------------------------------------------------------------------
// Per-row correction (gathered target terms), done by a few threads per block
// ---------------------------------------------------------------------------
__device__ __forceinline__ void do_row_corr(
    const float* __restrict__ px, const float* __restrict__ py,
    const longlong2* __restrict__ tgt, int rows, int rowsPerBlock,
    int W, int H, float invW, float invH)
{
    int lane = (int)threadIdx.x;
    if (lane >= rowsPerBlock) return;
    int r = (int)blockIdx.x * rowsPerBlock + lane;
    if (r >= rows) return;
    longlong2 t = __ldg(tgt + r);
    int tx = (int)t.x; tx = tx < 0 ? 0 : (tx > W - 1 ? W - 1 : tx);
    int ty = (int)t.y; ty = ty < 0 ? 0 : (ty > H - 1 ? H - 1 : ty);
    float m = mask_of(t);
    float pxv = __ldg(px + (size_t)r * W + tx);
    float pyv = __ldg(py + (size_t)r * H + ty);
    float lpx  = fmaxf(__logf(pxv), -100.0f);
    float l1px = clog1m(pxv);
    float lpy  = fmaxf(__logf(pyv), -100.0f);
    float l1py = clog1m(pyv);
    float corr = (l1px - lpx) * invW + (l1py - lpy) * invH;
    g_mask[r] = m;
    g_corr[r] = m * corr;
}

// ---------------------------------------------------------------------------
// Main streaming reduction (vectorized float4 path, mask inline from tgt)
// ---------------------------------------------------------------------------
template <int PR4>
__device__ __forceinline__ unsigned row_of(unsigned i, unsigned pr4) {
    return (PR4 > 0) ? (i / (unsigned)PR4) : (i / pr4);
}

__device__ __forceinline__ float sum4(float4 v) {
    float s = clog1m(v.x);
    s += clog1m(v.y);
    s += clog1m(v.z);
    s += clog1m(v.w);
    return s;
}

template <int PR4>
__device__ __forceinline__ float region_sum(const float4* __restrict__ p,
                                            const longlong2* __restrict__ tgt,
                                            unsigned n4, unsigned pr4,
                                            unsigned start, unsigned stride)
{
    float a0 = 0.f, a1 = 0.f, a2 = 0.f, a3 = 0.f;
    unsigned i = start;
    for (; i + 3u * stride < n4; i += 4u * stride) {
        unsigned i0 = i, i1 = i + stride, i2 = i + 2u * stride, i3 = i + 3u * stride;
        float4 v0 = __ldcs(p + i0);
        float4 v1 = __ldcs(p + i1);
        float4 v2 = __ldcs(p + i2);
        float4 v3 = __ldcs(p + i3);
        longlong2 t0 = __ldg(tgt + row_of<PR4>(i0, pr4));
        longlong2 t1 = __ldg(tgt + row_of<PR4>(i1, pr4));
        longlong2 t2 = __ldg(tgt + row_of<PR4>(i2, pr4));
        longlong2 t3 = __ldg(tgt + row_of<PR4>(i3, pr4));
        a0 += mask_of(t0) * sum4(v0);
        a1 += mask_of(t1) * sum4(v1);
        a2 += mask_of(t2) * sum4(v2);
        a3 += mask_of(t3) * sum4(v3);
    }
    for (; i < n4; i += stride) {
        float4 v = __ldcs(p + i);
        longlong2 t = __ldg(tgt + row_of<PR4>(i, pr4));
        a0 += mask_of(t) * sum4(v);
    }
    return (a0 + a1) + (a2 + a3);
}

__device__ __forceinline__ void block_reduce_store(float acc, float scale)
{
    __shared__ float sh[BLK / 32];
    unsigned tid = threadIdx.x;
    #pragma unroll
    for (int o = 16; o > 0; o >>= 1)
        acc += __shfl_down_sync(0xffffffffu, acc, o);
    if ((tid & 31u) == 0) sh[tid >> 5] = acc;
    __syncthreads();
    if (tid < (BLK / 32)) {
        float v = sh[tid];
        #pragma unroll
        for (int o = (BLK / 64); o > 0; o >>= 1)
            v += __shfl_down_sync(0xffu, v, o, BLK / 32);
        if (tid == 0) g_part[blockIdx.x] = v * scale;
    }
}

template <int PR4X, int PR4Y>
__global__ void __launch_bounds__(BLK) main_kernel(
    const float4* __restrict__ px4, const float4* __restrict__ py4,
    const longlong2* __restrict__ tgt,
    unsigned n4x, unsigned n4y, int blocksX, int blocksTotal,
    unsigned pr4x, unsigned pr4y, float invW, float invH,
    int rows, int rowsPerBlock, int W, int H)
{
    // per-row gathered corrections (consumed only by final_kernel)
    do_row_corr((const float*)px4, (const float*)py4, tgt, rows, rowsPerBlock,
                W, H, invW, invH);

    float acc, scale;
    unsigned tid = threadIdx.x;
    if ((int)blockIdx.x < blocksX) {
        unsigned stride = (unsigned)blocksX * (unsigned)BLK;
        acc = region_sum<PR4X>(px4, tgt, n4x, pr4x, blockIdx.x * (unsigned)BLK + tid, stride);
        scale = -invW;
    } else {
        unsigned bid = blockIdx.x - (unsigned)blocksX;
        unsigned nb = (unsigned)(blocksTotal - blocksX);
        unsigned stride = nb * (unsigned)BLK;
        acc = region_sum<PR4Y>(py4, tgt, n4y, pr4y, bid * (unsigned)BLK + tid, stride);
        scale = -invH;
    }
    block_reduce_store(acc, scale);
}

// Scalar fallback (W or H not divisible by 4) — correctness insurance only.
__global__ void __launch_bounds__(BLK) main_kernel_scalar(
    const float* __restrict__ px, const float* __restrict__ py,
    const longlong2* __restrict__ tgt,
    unsigned nx, unsigned ny, int blocksX, int blocksTotal,
    unsigned W, unsigned H, float invW, float invH,
    int rows, int rowsPerBlock)
{
    do_row_corr(px, py, tgt, rows, rowsPerBlock, (int)W, (int)H, invW, invH);

    float acc = 0.f, scale;
    unsigned tid = threadIdx.x;
    if ((int)blockIdx.x < blocksX) {
        unsigned stride = (unsigned)blocksX * (unsigned)BLK;
        for (unsigned i = blockIdx.x * (unsigned)BLK + tid; i < nx; i += stride) {
            longlong2 t = __ldg(tgt + i / W);
            acc += mask_of(t) * clog1m(__ldcs(px + i));
        }
        scale = -invW;
    } else {
        unsigned nb = (unsigned)(blocksTotal - blocksX);
        unsigned stride = nb * (unsigned)BLK;
        for (unsigned i = (blockIdx.x - (unsigned)blocksX) * (unsigned)BLK + tid; i < ny; i += stride) {
            longlong2 t = __ldg(tgt + i / H);
            acc += mask_of(t) * clog1m(__ldcs(py + i));
        }
        scale = -invH;
    }
    block_reduce_store(acc, scale);
}

// ---------------------------------------------------------------------------
// Final: deterministic double-precision reduction of corrections + partials
// ---------------------------------------------------------------------------
__global__ void final_kernel(int rows, int nb, float* __restrict__ out)
{
    __shared__ double sh0[BLK], sh1[BLK], sh2[BLK];
    unsigned tid = threadIdx.x;

    float c0 = 0.f, c1 = 0.f, c2 = 0.f, c3 = 0.f;
    float m0 = 0.f, m1 = 0.f, m2 = 0.f, m3 = 0.f;
    int r = (int)tid;
    for (; r + 3 * BLK < rows; r += 4 * BLK) {
        c0 += g_corr[r];           m0 += g_mask[r];
        c1 += g_corr[r + BLK];     m1 += g_mask[r + BLK];
        c2 += g_corr[r + 2 * BLK]; m2 += g_mask[r + 2 * BLK];
        c3 += g_corr[r + 3 * BLK]; m3 += g_mask[r + 3 * BLK];
    }
    for (; r < rows; r += BLK) { c0 += g_corr[r]; m0 += g_mask[r]; }

    float p0 = 0.f;
    for (int b = (int)tid; b < nb; b += BLK) p0 += g_part[b];

    sh0[tid] = (double)((c0 + c1) + (c2 + c3));
    sh1[tid] = (double)((m0 + m1) + (m2 + m3));
    sh2[tid] = (double)p0;
    __syncthreads();
    for (int s = BLK / 2; s > 0; s >>= 1) {
        if ((int)tid < s) {
            sh0[tid] += sh0[tid + s];
            sh1[tid] += sh1[tid + s];
            sh2[tid] += sh2[tid + s];
        }
        __syncthreads();
    }
    if (tid == 0) {
        double denom = sh1[0] > 1.0 ? sh1[0] : 1.0;
        out[0] = (float)((sh0[0] + sh2[0]) / denom);
    }
}

// ---------------------------------------------------------------------------
// Launch
// ---------------------------------------------------------------------------
extern "C" void kernel_launch(void* const* d_in, const int* in_sizes, int n_in,
                              void* d_out, int out_size)
{
    const float*     px  = (const float*)d_in[0];
    const float*     py  = (const float*)d_in[1];
    const longlong2* tgt = (const longlong2*)d_in[2];
    float* out = (float*)d_out;

    int rows = in_sizes[2] / 2;
    int W = in_sizes[0] / rows;
    int H = in_sizes[1] / rows;
    float invW = 1.0f / (float)W;
    float invH = 1.0f / (float)H;

    int blocksTotal = 1184;                  // ~8 blocks/SM worth of work, <= MAXPART
    int rowsPerBlock = (rows + blocksTotal - 1) / blocksTotal;
    if (rowsPerBlock > BLK) rowsPerBlock = BLK;   // safety (rows <= BLK*blocksTotal assumed)

    unsigned long long nx = (unsigned long long)rows * (unsigned long long)W;
    unsigned long long ny = (unsigned long long)rows * (unsigned long long)H;
    int blocksX = (int)((nx * (unsigned long long)blocksTotal) / (nx + ny));
    if (blocksX < 1) blocksX = 1;
    if (blocksX > blocksTotal - 1) blocksX = blocksTotal - 1;

    if ((W % 4) == 0 && (H % 4) == 0) {
        unsigned n4x = (unsigned)(nx / 4ull);
        unsigned n4y = (unsigned)(ny / 4ull);
        unsigned pr4x = (unsigned)(W / 4);
        unsigned pr4y = (unsigned)(H / 4);
        if (pr4x == 480u && pr4y == 270u) {
            main_kernel<480, 270><<<blocksTotal, BLK>>>(
                (const float4*)px, (const float4*)py, tgt,
                n4x, n4y, blocksX, blocksTotal, pr4x, pr4y, invW, invH,
                rows, rowsPerBlock, W, H);
        } else {
            main_kernel<0, 0><<<blocksTotal, BLK>>>(
                (const float4*)px, (const float4*)py, tgt,
                n4x, n4y, blocksX, blocksTotal, pr4x, pr4y, invW, invH,
                rows, rowsPerBlock, W, H);
        }
    } else {
        main_kernel_scalar<<<blocksTotal, BLK>>>(
            px, py, tgt, (unsigned)nx, (unsigned)ny, blocksX, blocksTotal,
            (unsigned)W, (unsigned)H, invW, invH, rows, rowsPerBlock);
    }

    final_kernel<<<1, BLK>>>(rows, blocksTotal, out);
}

// round 7
// speedup vs baseline: 1.1404x; 1.1404x over previous
#include <cuda_runtime.h>

#define BLK 256
#define MAXPART 8192

__device__ float g_part[MAXPART];  // per-block loss partials
__device__ float g_cnt[MAXPART];   // per-block valid-count partials
__device__ int   g_ticket;         // last-block-done ticket (reset by last block)

__device__ __forceinline__ float clog1m(float p) {
    // clamp(log(1-p), -100)  (torch BCELoss clamp)
    return fmaxf(__logf(1.0f - p), -100.0f);
}
__device__ __forceinline__ float clogp(float p) {
    return fmaxf(__logf(p), -100.0f);
}

__device__ __forceinline__ float warp_sum(float v) {
    #pragma unroll
    for (int o = 16; o > 0; o >>= 1)
        v += __shfl_down_sync(0xffffffffu, v, o);
    return v;
}

// Warp-cooperative row reduction over float4 row data.
// Returns (l1p[t] - lp[t]) - sum_i l1p[i]   (== row_loss * L, pre-mask)
// FULL = full 32-lane f4 iterations, REM = residual f4 count (lane < REM).
template <int FULL, int REM>
__device__ __forceinline__ float row_reduce_f4(const float4* __restrict__ rowp,
                                               int lane, int t_idx)
{
    int f4i = t_idx >> 2, t_it = f4i >> 5, t_lane = f4i & 31, t_e = t_idx & 3;
    float a = 0.f;
    #pragma unroll
    for (int it = 0; it < FULL; ++it) {
        float4 v = __ldcs(rowp + it * 32 + lane);
        a -= (clog1m(v.x) + clog1m(v.y)) + (clog1m(v.z) + clog1m(v.w));
        if (it == t_it && lane == t_lane) {
            float pv = t_e == 0 ? v.x : (t_e == 1 ? v.y : (t_e == 2 ? v.z : v.w));
            a += clog1m(pv) - clogp(pv);
        }
    }
    if (REM > 0 && lane < REM) {
        float4 v = __ldcs(rowp + FULL * 32 + lane);
        a -= (clog1m(v.x) + clog1m(v.y)) + (clog1m(v.z) + clog1m(v.w));
        if (FULL == t_it && lane == t_lane) {
            float pv = t_e == 0 ? v.x : (t_e == 1 ? v.y : (t_e == 2 ? v.z : v.w));
            a += clog1m(pv) - clogp(pv);
        }
    }
    return warp_sum(a);
}

// Runtime-length float4 variant (W,H divisible by 4 but not 1920/1080).
__device__ __forceinline__ float row_reduce_f4_rt(const float4* __restrict__ rowp,
                                                  int lane, int t_idx, int pr4)
{
    int f4i = t_idx >> 2, t_e = t_idx & 3;
    float a = 0.f;
    for (int j = lane; j < pr4; j += 32) {
        float4 v = __ldcs(rowp + j);
        a -= (clog1m(v.x) + clog1m(v.y)) + (clog1m(v.z) + clog1m(v.w));
        if (j == f4i) {
            float pv = t_e == 0 ? v.x : (t_e == 1 ? v.y : (t_e == 2 ? v.z : v.w));
            a += clog1m(pv) - clogp(pv);
        }
    }
    return warp_sum(a);
}

// Scalar variant (arbitrary W, H).
__device__ __forceinline__ float row_reduce_sc(const float* __restrict__ rowp,
                                               int lane, int t_idx, int L)
{
    float a = 0.f;
    for (int j = lane; j < L; j += 32) {
        float p = __ldcs(rowp + j);
        a -= clog1m(p);
        if (j == t_idx) a += clog1m(p) - clogp(p);
    }
    return warp_sum(a);
}

// MODE: 0 = compile-time 1920x1080 fast path, 1 = runtime float4, 2 = scalar
template <int MODE>
__global__ void __launch_bounds__(BLK) fused_kernel(
    const float* __restrict__ px, const float* __restrict__ py,
    const longlong2* __restrict__ tgt, float* __restrict__ out,
    int rows, int W, int H, float invW, float invH)
{
    const int lane = (int)threadIdx.x & 31;
    const int wid  = (int)threadIdx.x >> 5;
    const int gw   = (int)blockIdx.x * (BLK / 32) + wid;
    const int nw   = (int)gridDim.x * (BLK / 32);
    const int pr4x = W >> 2, pr4y = H >> 2;

    float loss = 0.f, cnt = 0.f;
    for (int r = gw; r < rows; r += nw) {
        longlong2 t = __ldg(tgt + r);
        // after clamping, tx==0 iff t.x<=0 (same for y); invalid iff both clamp to 0
        float m = (t.x > 0 || t.y > 0) ? 1.0f : 0.0f;
        int tx = (int)t.x; tx = tx < 0 ? 0 : (tx > W - 1 ? W - 1 : tx);
        int ty = (int)t.y; ty = ty < 0 ? 0 : (ty > H - 1 ? H - 1 : ty);

        float Sx, Sy;
        if (MODE == 0) {
            const float4* rx = (const float4*)px + (size_t)r * 480;
            const float4* ry = (const float4*)py + (size_t)r * 270;
            Sx = row_reduce_f4<15, 0>(rx, lane, tx);   // 480 f4 = 15*32
            Sy = row_reduce_f4<8, 14>(ry, lane, ty);   // 270 f4 = 8*32 + 14
        } else if (MODE == 1) {
            const float4* rx = (const float4*)px + (size_t)r * pr4x;
            const float4* ry = (const float4*)py + (size_t)r * pr4y;
            Sx = row_reduce_f4_rt(rx, lane, tx, pr4x);
            Sy = row_reduce_f4_rt(ry, lane, ty, pr4y);
        } else {
            Sx = row_reduce_sc(px + (size_t)r * W, lane, tx, W);
            Sy = row_reduce_sc(py + (size_t)r * H, lane, ty, H);
        }
        if (lane == 0) {
            loss += m * (Sx * invW + Sy * invH);
            cnt  += m;
        }
    }

    // block reduce warp-leader partials
    __shared__ float sl[BLK / 32], sc[BLK / 32];
    __shared__ float s_islast;
    if (lane == 0) { sl[wid] = loss; sc[wid] = cnt; }
    __syncthreads();
    if (threadIdx.x == 0) {
        float L = 0.f, C = 0.f;
        #pragma unroll
        for (int i = 0; i < BLK / 32; i++) { L += sl[i]; C += sc[i]; }
        g_part[blockIdx.x] = L;
        g_cnt[blockIdx.x]  = C;
        __threadfence();
        int ticket = atomicAdd(&g_ticket, 1);
        s_islast = (ticket == (int)gridDim.x - 1) ? 1.f : 0.f;
    }
    __syncthreads();

    if (s_islast != 0.f) {
        __threadfence();  // acquire: partials of all other blocks are visible
        double dl = 0.0, dc = 0.0;
        for (int i = (int)threadIdx.x; i < (int)gridDim.x; i += BLK) {
            dl += (double)__ldcg(&g_part[i]);
            dc += (double)__ldcg(&g_cnt[i]);
        }
        __shared__ double shl[BLK], shc[BLK];
        shl[threadIdx.x] = dl; shc[threadIdx.x] = dc;
        __syncthreads();
        for (int s = BLK / 2; s > 0; s >>= 1) {
            if ((int)threadIdx.x < s) {
                shl[threadIdx.x] += shl[threadIdx.x + s];
                shc[threadIdx.x] += shc[threadIdx.x + s];
            }
            __syncthreads();
        }
        if (threadIdx.x == 0) {
            double denom = shc[0] > 1.0 ? shc[0] : 1.0;
            out[0] = (float)(shl[0] / denom);
            g_ticket = 0;  // reset for next (graph-replayed) call
        }
    }
}

extern "C" void kernel_launch(void* const* d_in, const int* in_sizes, int n_in,
                              void* d_out, int out_size)
{
    const float*     px  = (const float*)d_in[0];
    const float*     py  = (const float*)d_in[1];
    const longlong2* tgt = (const longlong2*)d_in[2];
    float* out = (float*)d_out;

    int rows = in_sizes[2] / 2;
    int W = in_sizes[0] / rows;
    int H = in_sizes[1] / rows;
    float invW = 1.0f / (float)W;
    float invH = 1.0f / (float)H;

    // one warp per row pair when possible
    int blocks = (rows + (BLK / 32) - 1) / (BLK / 32);
    if (blocks > 2048) blocks = 2048;
    if (blocks > MAXPART) blocks = MAXPART;
    if (blocks < 1) blocks = 1;

    if (W == 1920 && H == 1080) {
        fused_kernel<0><<<blocks, BLK>>>(px, py, tgt, out, rows, W, H, invW, invH);
    } else if ((W % 4) == 0 && (H % 4) == 0) {
        fused_kernel<1><<<blocks, BLK>>>(px, py, tgt, out, rows, W, H, invW, invH);
    } else {
        fused_kernel<2><<<blocks, BLK>>>(px, py, tgt, out, rows, W, H, invW, invH);
    }
}

// round 14
// speedup vs baseline: 1.5807x; 1.3861x over previous
#include <cuda_runtime.h>

#define BLK 256
#define MAXPART 8192

__device__ float g_part[MAXPART];  // per-block loss partials
__device__ float g_cnt[MAXPART];   // per-block valid-count partials
__device__ int   g_ticket;         // last-block-done ticket (reset by last block)

__device__ __forceinline__ float clog1m(float p) {
    return fmaxf(__logf(1.0f - p), -100.0f);   // torch BCELoss clamp
}
__device__ __forceinline__ float clogp(float p) {
    return fmaxf(__logf(p), -100.0f);
}
__device__ __forceinline__ float mask_of(longlong2 t) {
    // after clamp to [0,L-1], tx==0 iff t.x<=0; invalid iff both clamp to 0
    return (t.x > 0 || t.y > 0) ? 1.0f : 0.0f;
}
__device__ __forceinline__ float sum4(float4 v) {
    return (clog1m(v.x) + clog1m(v.y)) + (clog1m(v.z) + clog1m(v.w));
}

template <int PPR>
__device__ __forceinline__ unsigned rowq(unsigned q, unsigned ppr) {
    return (PPR > 0) ? (q / (unsigned)PPR) : (q / ppr);
}

// Streaming sum of clog1m over a region addressed in 32B pairs of float4.
// PPR = pairs per row (compile-time fast path), ppr = runtime value.
template <int PPR>
__device__ __forceinline__ float region_pairs(const float4* __restrict__ p,
                                              const longlong2* __restrict__ tgt,
                                              unsigned np, unsigned ppr,
                                              unsigned start, unsigned stride)
{
    float a0 = 0.f, a1 = 0.f, a2 = 0.f, a3 = 0.f;
    unsigned q = start;
    for (; q + 3u * stride < np; q += 4u * stride) {
        unsigned q0 = q, q1 = q + stride, q2 = q + 2u * stride, q3 = q + 3u * stride;
        // batch all loads before any compute (8x LDG.128 + 4x LDG.64 in flight)
        float4 u0 = __ldcs(p + 2u * q0),     w0 = __ldcs(p + 2u * q0 + 1u);
        float4 u1 = __ldcs(p + 2u * q1),     w1 = __ldcs(p + 2u * q1 + 1u);
        float4 u2 = __ldcs(p + 2u * q2),     w2 = __ldcs(p + 2u * q2 + 1u);
        float4 u3 = __ldcs(p + 2u * q3),     w3 = __ldcs(p + 2u * q3 + 1u);
        longlong2 t0 = __ldg(tgt + rowq<PPR>(q0, ppr));
        longlong2 t1 = __ldg(tgt + rowq<PPR>(q1, ppr));
        longlong2 t2 = __ldg(tgt + rowq<PPR>(q2, ppr));
        longlong2 t3 = __ldg(tgt + rowq<PPR>(q3, ppr));
        a0 += mask_of(t0) * (sum4(u0) + sum4(w0));
        a1 += mask_of(t1) * (sum4(u1) + sum4(w1));
        a2 += mask_of(t2) * (sum4(u2) + sum4(w2));
        a3 += mask_of(t3) * (sum4(u3) + sum4(w3));
    }
    for (; q < np; q += stride) {
        float4 u = __ldcs(p + 2u * q), w = __ldcs(p + 2u * q + 1u);
        longlong2 t = __ldg(tgt + rowq<PPR>(q, ppr));
        a0 += mask_of(t) * (sum4(u) + sum4(w));
    }
    return (a0 + a1) + (a2 + a3);
}

// MODE: 0 = compile-time 1920x1080 (PPR 240/135), 1 = runtime pairs (W%8==0,H%8==0),
//       2 = scalar fallback (any W,H)
template <int MODE>
__global__ void __launch_bounds__(BLK, 4) fused_kernel(
    const float* __restrict__ px, const float* __restrict__ py,
    const longlong2* __restrict__ tgt, float* __restrict__ out,
    int rows, int W, int H, float invW, float invH, int blocksX)
{
    const unsigned tid = threadIdx.x;
    float loss = 0.f, cnt = 0.f;

    // ---- per-row gathered corrections + valid count (few threads per block) ----
    {
        int rpb = (rows + (int)gridDim.x - 1) / (int)gridDim.x;
        int r0 = (int)blockIdx.x * rpb;
        int r1 = r0 + rpb; if (r1 > rows) r1 = rows;
        for (int r = r0 + (int)tid; r < r1; r += BLK) {
            longlong2 t = __ldg(tgt + r);
            float m = mask_of(t);
            int tx = (int)t.x; tx = tx < 0 ? 0 : (tx > W - 1 ? W - 1 : tx);
            int ty = (int)t.y; ty = ty < 0 ? 0 : (ty > H - 1 ? H - 1 : ty);
            float pxv = __ldg(px + (size_t)r * W + tx);
            float pyv = __ldg(py + (size_t)r * H + ty);
            float corr = (clog1m(pxv) - clogp(pxv)) * invW
                       + (clog1m(pyv) - clogp(pyv)) * invH;
            loss += m * corr;
            cnt  += m;
        }
    }

    // ---- bulk streaming: block handles X region or Y region ----
    if (MODE != 2) {
        unsigned pprx = (unsigned)(W >> 3), ppry = (unsigned)(H >> 3);
        unsigned npx = (unsigned)rows * pprx, npy = (unsigned)rows * ppry;
        float S, scale;
        if ((int)blockIdx.x < blocksX) {
            unsigned stride = (unsigned)blocksX * BLK;
            unsigned start  = blockIdx.x * BLK + tid;
            S = (MODE == 0)
                ? region_pairs<240>((const float4*)px, tgt, npx, pprx, start, stride)
                : region_pairs<0>  ((const float4*)px, tgt, npx, pprx, start, stride);
            scale = invW;
        } else {
            unsigned nb = gridDim.x - (unsigned)blocksX;
            unsigned stride = nb * BLK;
            unsigned start  = (blockIdx.x - (unsigned)blocksX) * BLK + tid;
            S = (MODE == 0)
                ? region_pairs<135>((const float4*)py, tgt, npy, ppry, start, stride)
                : region_pairs<0>  ((const float4*)py, tgt, npy, ppry, start, stride);
            scale = invH;
        }
        loss -= scale * S;
    } else {
        unsigned nx = (unsigned)rows * (unsigned)W, ny = (unsigned)rows * (unsigned)H;
        float S = 0.f, scale;
        if ((int)blockIdx.x < blocksX) {
            unsigned stride = (unsigned)blocksX * BLK;
            for (unsigned i = blockIdx.x * BLK + tid; i < nx; i += stride) {
                longlong2 t = __ldg(tgt + i / (unsigned)W);
                S += mask_of(t) * clog1m(__ldcs(px + i));
            }
            scale = invW;
        } else {
            unsigned nb = gridDim.x - (unsigned)blocksX;
            unsigned stride = nb * BLK;
            for (unsigned i = (blockIdx.x - (unsigned)blocksX) * BLK + tid; i < ny; i += stride) {
                longlong2 t = __ldg(tgt + i / (unsigned)H);
                S += mask_of(t) * clog1m(__ldcs(py + i));
            }
            scale = invH;
        }
        loss -= scale * S;
    }

    // ---- block reduce (loss, cnt) ----
    __shared__ float sl[BLK / 32], sc[BLK / 32];
    __shared__ float s_islast;
    #pragma unroll
    for (int o = 16; o > 0; o >>= 1) {
        loss += __shfl_down_sync(0xffffffffu, loss, o);
        cnt  += __shfl_down_sync(0xffffffffu, cnt, o);
    }
    if ((tid & 31u) == 0) { sl[tid >> 5] = loss; sc[tid >> 5] = cnt; }
    __syncthreads();
    if (tid == 0) {
        float L = 0.f, C = 0.f;
        #pragma unroll
        for (int i = 0; i < BLK / 32; i++) { L += sl[i]; C += sc[i]; }
        g_part[blockIdx.x] = L;
        g_cnt[blockIdx.x]  = C;
        __threadfence();
        int ticket = atomicAdd(&g_ticket, 1);
        s_islast = (ticket == (int)gridDim.x - 1) ? 1.f : 0.f;
    }
    __syncthreads();

    // ---- last block finishes (fixed-order double sum -> deterministic) ----
    if (s_islast != 0.f) {
        __threadfence();
        double dl = 0.0, dc = 0.0;
        for (int i = (int)tid; i < (int)gridDim.x; i += BLK) {
            dl += (double)__ldcg(&g_part[i]);
            dc += (double)__ldcg(&g_cnt[i]);
        }
        __shared__ double shl[BLK], shc[BLK];
        shl[tid] = dl; shc[tid] = dc;
        __syncthreads();
        for (int s = BLK / 2; s > 0; s >>= 1) {
            if ((int)tid < s) { shl[tid] += shl[tid + s]; shc[tid] += shc[tid + s]; }
            __syncthreads();
        }
        if (tid == 0) {
            double denom = shc[0] > 1.0 ? shc[0] : 1.0;
            out[0] = (float)(shl[0] / denom);
            g_ticket = 0;  // reset for next graph replay
        }
    }
}

extern "C" void kernel_launch(void* const* d_in, const int* in_sizes, int n_in,
                              void* d_out, int out_size)
{
    const float*     px  = (const float*)d_in[0];
    const float*     py  = (const float*)d_in[1];
    const longlong2* tgt = (const longlong2*)d_in[2];
    float* out = (float*)d_out;

    int rows = in_sizes[2] / 2;
    int W = in_sizes[0] / rows;
    int H = in_sizes[1] / rows;
    float invW = 1.0f / (float)W;
    float invH = 1.0f / (float)H;

    int blocks = 592;  // 4 blocks/SM x 148 SMs, single wave at 64 regs
    if (blocks > MAXPART) blocks = MAXPART;

    unsigned long long nx = (unsigned long long)rows * (unsigned long long)W;
    unsigned long long ny = (unsigned long long)rows * (unsigned long long)H;
    int blocksX = (int)((nx * (unsigned long long)blocks) / (nx + ny));
    if (blocksX < 1) blocksX = 1;
    if (blocksX > blocks - 1) blocksX = blocks - 1;

    if (W == 1920 && H == 1080) {
        fused_kernel<0><<<blocks, BLK>>>(px, py, tgt, out, rows, W, H, invW, invH, blocksX);
    } else if ((W % 8) == 0 && (H % 8) == 0) {
        fused_kernel<1><<<blocks, BLK>>>(px, py, tgt, out, rows, W, H, invW, invH, blocksX);
    } else {
        fused_kernel<2><<<blocks, BLK>>>(px, py, tgt, out, rows, W, H, invW, invH, blocksX);
    }
}